// round 14
// baseline (speedup 1.0000x reference)
#include <cuda_runtime.h>
#include <cuda_fp16.h>

// BezierAlign, GB300 (sm_103a).
// input  [2,256,160,160] f32 NCHW,  rois [256,17] f32,  out [256,256,16,64] f32.
//
// Pass 1: NCHW f32 -> NHWC fp16 scratch.
// Pass 2: block = 32 positions (consecutive ow), 16 warps. Geometry: warp 0
//         lanes each build one position's pixel list (offset, fp16x2 weight);
//         lanes 0-15 then merge adjacent-ow pairs into union lists with dual
//         weights (footprints overlap ~35% at bin_w/2 sample spacing). Warp w
//         gathers positions 2w/2w+1 together: per unique pixel one LDG.128 +
//         8 HFMA2. Staging via XOR-swizzled smem -> coalesced NCHW stores.

namespace {

constexpr int OUT_H = 16;
constexpr int OUT_W = 64;
constexpr int C_    = 256;
constexpr int H_    = 160;
constexpr int W_    = 160;
constexpr int HW_   = H_ * W_;
constexpr int R_    = 256;
constexpr float SPATIAL_SCALE = 0.25f;
constexpr int POS_PER_BLK = 32;            // 16 warps x 2 positions
constexpr int SOUT_STRIDE = C_ + 4;        // 260 floats; rows 16B-aligned

} // namespace

// 26.2 MB NHWC fp16 scratch: [N][H*W][C]
__device__ __align__(16) __half g_nhwc[2 * HW_ * C_];

namespace {

// ---------------------------------------------------------------------------
// Pass 1: NCHW f32 -> NHWC fp16
// ---------------------------------------------------------------------------
__global__ void __launch_bounds__(256)
transpose_kernel(const float* __restrict__ in)
{
    __shared__ float tile[32][33];
    int n   = blockIdx.z;
    int hw0 = blockIdx.x * 32;
    int c0  = blockIdx.y * 32;
    int t   = threadIdx.x;

    {
        int ci = t >> 3;
        int hv = (t & 7) * 4;
        float4 v = *reinterpret_cast<const float4*>(
            in + ((size_t)n * C_ + c0 + ci) * HW_ + hw0 + hv);
        tile[ci][hv + 0] = v.x;
        tile[ci][hv + 1] = v.y;
        tile[ci][hv + 2] = v.z;
        tile[ci][hv + 3] = v.w;
    }
    __syncthreads();
    {
        int hwi = t >> 3;
        int cv  = (t & 7) * 4;
        __half2 h0 = __floats2half2_rn(tile[cv + 0][hwi], tile[cv + 1][hwi]);
        __half2 h1 = __floats2half2_rn(tile[cv + 2][hwi], tile[cv + 3][hwi]);
        uint2 o;
        o.x = *reinterpret_cast<unsigned int*>(&h0);
        o.y = *reinterpret_cast<unsigned int*>(&h1);
        *reinterpret_cast<uint2*>(
            g_nhwc + ((size_t)n * HW_ + hw0 + hwi) * C_ + c0 + cv) = o;
    }
}

// ---------------------------------------------------------------------------
// Pass 2: gather
// ---------------------------------------------------------------------------
__device__ __forceinline__ float bez(float p0, float p1, float p2, float p3, float t) {
    float mt = 1.0f - t;
    return mt*mt*mt*p0 + 3.0f*t*mt*mt*p1 + 3.0f*t*t*mt*p2 + t*t*t*p3;
}

struct DimS { int lo, hi; float wlo, whi; };

__device__ __forceinline__ DimS samp(float coord, int LIMIT) {
    bool valid = (coord > -1.0f) && (coord < (float)LIMIT);
    float c = fmaxf(coord, 0.0f);
    int lo = min((int)floorf(c), LIMIT - 1);
    int hi = min(lo + 1, LIMIT - 1);
    if (lo >= LIMIT - 1) c = (float)lo;
    float l = c - (float)lo;
    float h = 1.0f - l;
    if (!valid) { l = 0.0f; h = 0.0f; }
    DimS d; d.lo = lo; d.hi = hi; d.wlo = h; d.whi = l;
    return d;
}

__device__ __forceinline__ void merge2(const DimS& a, const DimS& b,
                                       int cs[4], float cw[4]) {
    if (b.lo == a.lo) {
        cs[0] = a.lo; cw[0] = a.wlo + b.wlo;
        cs[1] = a.hi; cw[1] = a.whi + b.whi;
        cs[2] = a.lo; cw[2] = 0.0f;
        cs[3] = a.lo; cw[3] = 0.0f;
    } else if (b.lo == a.hi) {
        cs[0] = a.lo; cw[0] = a.wlo;
        cs[1] = a.hi; cw[1] = a.whi + b.wlo;
        cs[2] = b.hi; cw[2] = b.whi;
        cs[3] = a.lo; cw[3] = 0.0f;
    } else {
        cs[0] = a.lo; cw[0] = a.wlo;
        cs[1] = a.hi; cw[1] = a.whi;
        cs[2] = b.lo; cw[2] = b.wlo;
        cs[3] = b.hi; cw[3] = b.whi;
    }
}

__global__ void __launch_bounds__(512, 3)
gather_kernel(const float* __restrict__ rois, float* __restrict__ out)
{
    __shared__ int2  s_pix[POS_PER_BLK][16];     // per-position lists
    __shared__ int   s_np[POS_PER_BLK];
    __shared__ int4  s_m[16][32];                // merged pair lists
    __shared__ int   s_mn[16];
    __shared__ __align__(16) float s_out[POS_PER_BLK][SOUT_STRIDE];

    // block -> (r, oh, ow0);  8192 blocks = 256 r * 16 oh * 2 chunks of 32 ow
    int bid = blockIdx.x;
    int r   = bid >> 5;
    int oh  = (bid >> 1) & 15;
    int ow0 = (bid & 1) << 5;

    int tid  = threadIdx.x;
    int warp = tid >> 5;
    int lane = tid & 31;

    // ---- geometry: warp 0, one position per lane ---------------------------
    if (warp == 0) {
        int ow = ow0 + lane;
        const float* roi = rois + r * 17;
        int bi = (int)__ldg(roi);

        float px[8], py[8];
#pragma unroll
        for (int k = 0; k < 8; ++k) {
            px[k] = __ldg(roi + 1 + 2 * k) * SPATIAL_SCALE;
            py[k] = __ldg(roi + 2 + 2 * k) * SPATIAL_SCALE;
        }

        float u = (float)ow * (1.0f / OUT_W);
        float v = (float)oh * (1.0f / OUT_H);

        float x0 = bez(px[0], px[1], px[2], px[3], u);
        float y0 = bez(py[0], py[1], py[2], py[3], u);
        float x1 = bez(px[4], px[5], px[6], px[7], u);
        float y1 = bez(py[4], py[5], py[6], py[7], u);

        float xc = x1 * v + x0 * (1.0f - v) - 0.5f;   // ALIGNED offset
        float yc = y1 * v + y0 * (1.0f - v) - 0.5f;

        float roi_w = fmaxf(fabsf(px[0] - px[3]), fabsf(px[4] - px[7]));
        float roi_h = fmaxf(fabsf(py[0] - py[3]), fabsf(py[4] - py[7]));
        float bin_h = roi_h * (1.0f / OUT_H);
        float bin_w = roi_w * (1.0f / OUT_W);

        float ya = yc - 0.25f * bin_h;
        float yb = yc + 0.25f * bin_h;
        float xa = xc - 0.25f * bin_w;
        float xb = xc + 0.25f * bin_w;

        DimS sya = samp(ya, H_), syb = samp(yb, H_);
        DimS sxa = samp(xa, W_), sxb = samp(xb, W_);

        int   ycs[4], xcs[4];
        float ywt[4], xwt[4];
        merge2(sya, syb, ycs, ywt);
        merge2(sxa, sxb, xcs, xwt);

        int base_bi = bi * (HW_ * C_ * 2);           // byte offset
        int n = 0;
#pragma unroll
        for (int iy = 0; iy < 4; ++iy) {
            float wy = ywt[iy];
            if (wy == 0.0f) continue;
            int rowoff = base_bi + ycs[iy] * (W_ * C_ * 2);
#pragma unroll
            for (int ix = 0; ix < 4; ++ix) {
                float wp = wy * xwt[ix];
                if (wp == 0.0f) continue;
                __half2 w2 = __float2half2_rn(wp * 0.25f);
                s_pix[lane][n] = make_int2(rowoff + xcs[ix] * (C_ * 2),
                                           *reinterpret_cast<int*>(&w2));
                ++n;
            }
        }
        s_np[lane] = n;
        __syncwarp();

        // ---- merge pairs (2m, 2m+1): lanes 0-15 ----------------------------
        if (lane < 16) {
            int pa = lane * 2, pb = pa + 1;
            int na = s_np[pa], nb = s_np[pb];
            unsigned matched = 0;
            int nm = 0;
            for (int i = 0; i < na; ++i) {
                int2 a = s_pix[pa][i];
                int wB = 0;
                for (int j = 0; j < nb; ++j) {
                    if (!((matched >> j) & 1u) && s_pix[pb][j].x == a.x) {
                        wB = s_pix[pb][j].y;
                        matched |= 1u << j;
                        break;
                    }
                }
                s_m[lane][nm++] = make_int4(a.x, a.y, wB, 0);
            }
            for (int j = 0; j < nb; ++j) {
                if (!((matched >> j) & 1u)) {
                    int2 b = s_pix[pb][j];
                    s_m[lane][nm++] = make_int4(b.x, 0, b.y, 0);
                }
            }
            s_mn[lane] = nm;
        }
    }
    __syncthreads();

    // ---- gather: warp w -> positions 2w, 2w+1 ------------------------------
    int nm = s_mn[warp];
    const char* basep = reinterpret_cast<const char*>(g_nhwc) + lane * 16;

    __half2 a0 = __float2half2_rn(0.f), a1 = a0, a2 = a0, a3 = a0;
    __half2 b0 = a0, b1 = a0, b2 = a0, b3 = a0;

#pragma unroll 4
    for (int i = 0; i < nm; ++i) {
        int4    e   = s_m[warp][i];
        uint4   raw = *reinterpret_cast<const uint4*>(basep + e.x);
        __half2 wA  = *reinterpret_cast<__half2*>(&e.y);
        __half2 wB  = *reinterpret_cast<__half2*>(&e.z);
        __half2 d0  = *reinterpret_cast<__half2*>(&raw.x);
        __half2 d1  = *reinterpret_cast<__half2*>(&raw.y);
        __half2 d2  = *reinterpret_cast<__half2*>(&raw.z);
        __half2 d3  = *reinterpret_cast<__half2*>(&raw.w);
        a0 = __hfma2(wA, d0, a0);  b0 = __hfma2(wB, d0, b0);
        a1 = __hfma2(wA, d1, a1);  b1 = __hfma2(wB, d1, b1);
        a2 = __hfma2(wA, d2, a2);  b2 = __hfma2(wB, d2, b2);
        a3 = __hfma2(wA, d3, a3);  b3 = __hfma2(wB, d3, b3);
    }

    // staging write, rows 2w and 2w+1; swizzle col ^= (row & 16)
    {
        int sw  = (2 * warp) & 16;                 // warp-uniform
        int col = (lane * 8) ^ sw;
        float2 fa0 = __half22float2(a0), fa1 = __half22float2(a1);
        float2 fa2 = __half22float2(a2), fa3 = __half22float2(a3);
        *reinterpret_cast<float4*>(&s_out[2 * warp][col]) =
            make_float4(fa0.x, fa0.y, fa1.x, fa1.y);
        *reinterpret_cast<float4*>(&s_out[2 * warp][col + 4]) =
            make_float4(fa2.x, fa2.y, fa3.x, fa3.y);
        float2 fb0 = __half22float2(b0), fb1 = __half22float2(b1);
        float2 fb2 = __half22float2(b2), fb3 = __half22float2(b3);
        *reinterpret_cast<float4*>(&s_out[2 * warp + 1][col]) =
            make_float4(fb0.x, fb0.y, fb1.x, fb1.y);
        *reinterpret_cast<float4*>(&s_out[2 * warp + 1][col + 4]) =
            make_float4(fb2.x, fb2.y, fb3.x, fb3.y);
    }

    __syncthreads();

    // ---- coalesced store: out[r][c][oh][ow0..ow0+31] -----------------------
    // thread t: c = t>>1, h = t&1 -> 16 floats (rows 16h..16h+15), 4x float4.
    // Read swizzle c^(16h) matches write swizzle (row&16).
    {
        int c   = tid >> 1;
        int h   = tid & 1;
        int csw = c ^ (h << 4);
        int p0  = h << 4;
        float* po = out + ((size_t)r * C_ + c) * (OUT_H * OUT_W)
                        + oh * OUT_W + ow0 + p0;
#pragma unroll
        for (int k = 0; k < 4; ++k) {
            float4 v;
            v.x = s_out[p0 + 4 * k + 0][csw];
            v.y = s_out[p0 + 4 * k + 1][csw];
            v.z = s_out[p0 + 4 * k + 2][csw];
            v.w = s_out[p0 + 4 * k + 3][csw];
            reinterpret_cast<float4*>(po)[k] = v;
        }
    }
}

} // namespace

extern "C" void kernel_launch(void* const* d_in, const int* in_sizes, int n_in,
                              void* d_out, int out_size) {
    const float* input = (const float*)d_in[0];   // [2,256,160,160] f32
    const float* rois  = (const float*)d_in[1];   // [256,17] f32
    float* out = (float*)d_out;                   // [256,256,16,64] f32

    dim3 tgrid(HW_ / 32, C_ / 32, 2);
    transpose_kernel<<<tgrid, 256>>>(input);

    int nblocks = R_ * OUT_H * (OUT_W / POS_PER_BLK);   // 8192
    gather_kernel<<<nblocks, 512>>>(rois, out);
}

// round 15
// speedup vs baseline: 2.3464x; 2.3464x over previous
#include <cuda_runtime.h>
#include <cuda_fp16.h>

// BezierAlign, GB300 (sm_103a).
// input  [2,256,160,160] f32 NCHW,  rois [256,17] f32,  out [256,256,16,64] f32.
//
// Pass 1: NCHW f32 -> NHWC fp16 scratch.
// Pass 2 (R13 structure): block = 16 positions. Threads 0-15 compute geometry
//         once per block, emitting pixel lists (byte offset, fp16x2 weight).
//         Warp w gathers 256 channels for position w: per pixel one LDG.128 +
//         4 HFMA2 (half2 accumulation, 4 blocks/SM). Staging smem uses swizzle
//         col ^= (row&12)<<1. Store phase: 4 consecutive lanes write one
//         channel's 64B row -> 8 wavefronts/STG instr (half of R13's 16),
//         conflict-free LDS (banks 16j+4i+c_local+8((w&3)^j) all distinct).

namespace {

constexpr int OUT_H = 16;
constexpr int OUT_W = 64;
constexpr int C_    = 256;
constexpr int H_    = 160;
constexpr int W_    = 160;
constexpr int HW_   = H_ * W_;
constexpr int R_    = 256;
constexpr float SPATIAL_SCALE = 0.25f;
constexpr int POS_PER_BLK = 16;
constexpr int SOUT_STRIDE = C_ + 4;   // 260 floats = 1040B; rows 16B-aligned

} // namespace

// 26.2 MB NHWC fp16 scratch: [N][H*W][C]
__device__ __align__(16) __half g_nhwc[2 * HW_ * C_];

namespace {

// ---------------------------------------------------------------------------
// Pass 1: NCHW f32 -> NHWC fp16
// ---------------------------------------------------------------------------
__global__ void __launch_bounds__(256)
transpose_kernel(const float* __restrict__ in)
{
    __shared__ float tile[32][33];
    int n   = blockIdx.z;
    int hw0 = blockIdx.x * 32;
    int c0  = blockIdx.y * 32;
    int t   = threadIdx.x;

    {
        int ci = t >> 3;
        int hv = (t & 7) * 4;
        float4 v = *reinterpret_cast<const float4*>(
            in + ((size_t)n * C_ + c0 + ci) * HW_ + hw0 + hv);
        tile[ci][hv + 0] = v.x;
        tile[ci][hv + 1] = v.y;
        tile[ci][hv + 2] = v.z;
        tile[ci][hv + 3] = v.w;
    }
    __syncthreads();
    {
        int hwi = t >> 3;
        int cv  = (t & 7) * 4;
        __half2 h0 = __floats2half2_rn(tile[cv + 0][hwi], tile[cv + 1][hwi]);
        __half2 h1 = __floats2half2_rn(tile[cv + 2][hwi], tile[cv + 3][hwi]);
        uint2 o;
        o.x = *reinterpret_cast<unsigned int*>(&h0);
        o.y = *reinterpret_cast<unsigned int*>(&h1);
        *reinterpret_cast<uint2*>(
            g_nhwc + ((size_t)n * HW_ + hw0 + hwi) * C_ + c0 + cv) = o;
    }
}

// ---------------------------------------------------------------------------
// Pass 2: gather
// ---------------------------------------------------------------------------
__device__ __forceinline__ float bez(float p0, float p1, float p2, float p3, float t) {
    float mt = 1.0f - t;
    return mt*mt*mt*p0 + 3.0f*t*mt*mt*p1 + 3.0f*t*t*mt*p2 + t*t*t*p3;
}

struct DimS { int lo, hi; float wlo, whi; };

__device__ __forceinline__ DimS samp(float coord, int LIMIT) {
    bool valid = (coord > -1.0f) && (coord < (float)LIMIT);
    float c = fmaxf(coord, 0.0f);
    int lo = min((int)floorf(c), LIMIT - 1);
    int hi = min(lo + 1, LIMIT - 1);
    if (lo >= LIMIT - 1) c = (float)lo;
    float l = c - (float)lo;
    float h = 1.0f - l;
    if (!valid) { l = 0.0f; h = 0.0f; }
    DimS d; d.lo = lo; d.hi = hi; d.wlo = h; d.whi = l;
    return d;
}

__device__ __forceinline__ void merge2(const DimS& a, const DimS& b,
                                       int cs[4], float cw[4]) {
    if (b.lo == a.lo) {
        cs[0] = a.lo; cw[0] = a.wlo + b.wlo;
        cs[1] = a.hi; cw[1] = a.whi + b.whi;
        cs[2] = a.lo; cw[2] = 0.0f;
        cs[3] = a.lo; cw[3] = 0.0f;
    } else if (b.lo == a.hi) {
        cs[0] = a.lo; cw[0] = a.wlo;
        cs[1] = a.hi; cw[1] = a.whi + b.wlo;
        cs[2] = b.hi; cw[2] = b.whi;
        cs[3] = a.lo; cw[3] = 0.0f;
    } else {
        cs[0] = a.lo; cw[0] = a.wlo;
        cs[1] = a.hi; cw[1] = a.whi;
        cs[2] = b.lo; cw[2] = b.wlo;
        cs[3] = b.hi; cw[3] = b.whi;
    }
}

__global__ void __launch_bounds__(POS_PER_BLK * 32, 4)
gather_kernel(const float* __restrict__ rois, float* __restrict__ out)
{
    __shared__ int2  s_pix[POS_PER_BLK][16];   // (byte offset, half2 weight bits)
    __shared__ int   s_n[POS_PER_BLK];
    __shared__ __align__(16) float s_out[POS_PER_BLK][SOUT_STRIDE];

    int bid = blockIdx.x;
    int r   = bid >> 6;
    int rem = bid & 63;
    int oh  = rem >> 2;
    int ow0 = (rem & 3) << 4;

    int tid  = threadIdx.x;
    int warp = tid >> 5;
    int lane = tid & 31;

    // ---- geometry: once per block, threads 0-15 ----------------------------
    if (tid < POS_PER_BLK) {
        int ow = ow0 + tid;
        const float* roi = rois + r * 17;
        int bi = (int)__ldg(roi);

        float px[8], py[8];
#pragma unroll
        for (int k = 0; k < 8; ++k) {
            px[k] = __ldg(roi + 1 + 2 * k) * SPATIAL_SCALE;
            py[k] = __ldg(roi + 2 + 2 * k) * SPATIAL_SCALE;
        }

        float u = (float)ow * (1.0f / OUT_W);
        float v = (float)oh * (1.0f / OUT_H);

        float x0 = bez(px[0], px[1], px[2], px[3], u);
        float y0 = bez(py[0], py[1], py[2], py[3], u);
        float x1 = bez(px[4], px[5], px[6], px[7], u);
        float y1 = bez(py[4], py[5], py[6], py[7], u);

        float xc = x1 * v + x0 * (1.0f - v) - 0.5f;   // ALIGNED offset
        float yc = y1 * v + y0 * (1.0f - v) - 0.5f;

        float roi_w = fmaxf(fabsf(px[0] - px[3]), fabsf(px[4] - px[7]));
        float roi_h = fmaxf(fabsf(py[0] - py[3]), fabsf(py[4] - py[7]));
        float bin_h = roi_h * (1.0f / OUT_H);
        float bin_w = roi_w * (1.0f / OUT_W);

        float ya = yc - 0.25f * bin_h;
        float yb = yc + 0.25f * bin_h;
        float xa = xc - 0.25f * bin_w;
        float xb = xc + 0.25f * bin_w;

        DimS sya = samp(ya, H_), syb = samp(yb, H_);
        DimS sxa = samp(xa, W_), sxb = samp(xb, W_);

        int   ycs[4], xcs[4];
        float ywt[4], xwt[4];
        merge2(sya, syb, ycs, ywt);
        merge2(sxa, sxb, xcs, xwt);

        int base_bi = bi * (HW_ * C_ * 2);           // byte offset
        int n = 0;
#pragma unroll
        for (int iy = 0; iy < 4; ++iy) {
            float wy = ywt[iy];
            if (wy == 0.0f) continue;
            int rowoff = base_bi + ycs[iy] * (W_ * C_ * 2);
#pragma unroll
            for (int ix = 0; ix < 4; ++ix) {
                float wp = wy * xwt[ix];
                if (wp == 0.0f) continue;
                __half2 w2 = __float2half2_rn(wp * 0.25f);
                s_pix[tid][n] = make_int2(rowoff + xcs[ix] * (C_ * 2),
                                          *reinterpret_cast<int*>(&w2));
                ++n;
            }
        }
        s_n[tid] = n;
    }
    __syncthreads();

    // ---- gather: warp per position, lane = 8 channels; half2 accumulate ----
    int npix = s_n[warp];
    const char* basep = reinterpret_cast<const char*>(g_nhwc) + lane * 16;

    __half2 acc0 = __float2half2_rn(0.f);
    __half2 acc1 = acc0, acc2 = acc0, acc3 = acc0;

#pragma unroll 8
    for (int i = 0; i < npix; ++i) {
        int2    pw  = s_pix[warp][i];
        __half2 wp2 = *reinterpret_cast<__half2*>(&pw.y);
        uint4   raw = *reinterpret_cast<const uint4*>(basep + pw.x);
        acc0 = __hfma2(wp2, *reinterpret_cast<__half2*>(&raw.x), acc0);
        acc1 = __hfma2(wp2, *reinterpret_cast<__half2*>(&raw.y), acc1);
        acc2 = __hfma2(wp2, *reinterpret_cast<__half2*>(&raw.z), acc2);
        acc3 = __hfma2(wp2, *reinterpret_cast<__half2*>(&raw.w), acc3);
    }

    // convert once, write to swizzled staging: col ^= (row & 12) << 1
    {
        float2 f0 = __half22float2(acc0);
        float2 f1 = __half22float2(acc1);
        float2 f2 = __half22float2(acc2);
        float2 f3 = __half22float2(acc3);
        int sw  = (warp & 12) << 1;                // 0,8,16,24 (multiple of 8)
        int col = (lane * 8) ^ sw;                 // stays 8-aligned
        *reinterpret_cast<float4*>(&s_out[warp][col]) =
            make_float4(f0.x, f0.y, f1.x, f1.y);
        *reinterpret_cast<float4*>(&s_out[warp][col + 4]) =
            make_float4(f2.x, f2.y, f3.x, f3.y);
    }

    __syncthreads();

    // ---- store: 4 consecutive lanes cover one channel's 64B (16 ow) row ----
    // lane = 4*c_local + j; thread writes float4 = positions 4j..4j+3 of
    // channel c = 8*warp + c_local (+128 per k-iteration).
    // LDS banks: 16j + 4i + c_local + 8*((warp&3)^j) -> all 32 distinct.
    {
        int c_local = lane >> 2;
        int j       = lane & 3;
#pragma unroll
        for (int k = 0; k < 2; ++k) {
            int c = 8 * warp + c_local + 128 * k;
            float4 v;
#pragma unroll
            for (int i = 0; i < 4; ++i) {
                int row = 4 * j + i;
                int csw = c ^ ((row & 12) << 1);
                (&v.x)[i] = s_out[row][csw];
            }
            float* po = out + ((size_t)r * C_ + c) * (OUT_H * OUT_W)
                            + oh * OUT_W + ow0;
            reinterpret_cast<float4*>(po)[j] = v;
        }
    }
}

} // namespace

extern "C" void kernel_launch(void* const* d_in, const int* in_sizes, int n_in,
                              void* d_out, int out_size) {
    const float* input = (const float*)d_in[0];   // [2,256,160,160] f32
    const float* rois  = (const float*)d_in[1];   // [256,17] f32
    float* out = (float*)d_out;                   // [256,256,16,64] f32

    dim3 tgrid(HW_ / 32, C_ / 32, 2);
    transpose_kernel<<<tgrid, 256>>>(input);

    int nblocks = R_ * OUT_H * (OUT_W / POS_PER_BLK);   // 16384
    gather_kernel<<<nblocks, POS_PER_BLK * 32>>>(rois, out);
}